// round 14
// baseline (speedup 1.0000x reference)
#include <cuda_runtime.h>
#include <cuda_fp16.h>
#include <cstdint>
#include <math.h>

#define BB 16
#define SS 1024
#define DD 1024
#define RCHUNKS 16

#define TMB 128
#define TNB 128
#define KC 32
#define STAGE_BYTES 32768
#define NSTAGE 3
#define GEMM_SMEM (NSTAGE * STAGE_BYTES)   // 98304

// ---------------- scratch ----------------
__device__ float g_scores[BB * SS * SS];
__device__ uint32_t g_Ah[16 * 64 * 64 * 32 * 4];
__device__ uint32_t g_Al[16 * 64 * 64 * 32 * 4];
__device__ uint32_t g_Bh[16 * 64 * 128 * 32 * 2];
__device__ uint32_t g_Bl[16 * 64 * 128 * 32 * 2];
__device__ float g_add_src[BB * SS];
__device__ float g_add_tgt[BB * SS];
__device__ float g_invT_src[BB];
__device__ float g_invT_tgt[BB];
__device__ float g_colmax[BB * SS], g_colsumT[BB * SS];
__device__ float g_colth[BB * SS];                // colmax + ln(1e-3 * colsum1)
__device__ float g_cm[RCHUNKS][BB * SS];
__device__ float g_c1[RCHUNKS][BB * SS];
__device__ float g_cT[RCHUNKS][BB * SS];

// ---------------- helpers ----------------
__device__ __forceinline__ uint32_t smem_u32(const void* p) {
    uint32_t a;
    asm("{ .reg .u64 t; cvta.to.shared.u64 t, %1; cvt.u32.u64 %0, t; }"
        : "=r"(a) : "l"(p));
    return a;
}

__device__ __forceinline__ void mma_f16(float* c, const uint32_t* a, const uint32_t* b) {
    asm volatile(
        "mma.sync.aligned.m16n8k16.row.col.f32.f16.f16.f32 "
        "{%0,%1,%2,%3}, {%4,%5,%6,%7}, {%8,%9}, {%0,%1,%2,%3};"
        : "+f"(c[0]), "+f"(c[1]), "+f"(c[2]), "+f"(c[3])
        : "r"(a[0]), "r"(a[1]), "r"(a[2]), "r"(a[3]), "r"(b[0]), "r"(b[1]));
}

__device__ __forceinline__ void cp16(uint32_t dst, const void* src) {
    asm volatile("cp.async.cg.shared.global [%0], [%1], 16;"
                 :: "r"(dst), "l"(src) : "memory");
}

#define LDS128(r, addr) \
    asm volatile("ld.shared.v4.b32 {%0,%1,%2,%3}, [%4];" \
        : "=r"((r)[0]), "=r"((r)[1]), "=r"((r)[2]), "=r"((r)[3]) : "r"(addr))
#define LDS64(r, addr) \
    asm volatile("ld.shared.v2.b32 {%0,%1}, [%2];" \
        : "=r"((r)[0]), "=r"((r)[1]) : "r"(addr))

__device__ __forceinline__ uint32_t pack_hi_lo(float x, float y, uint32_t& lo) {
    __half hx = __float2half_rn(x), hy = __float2half_rn(y);
    float lx = x - __half2float(hx), ly = y - __half2float(hy);
    __half2 h2 = __halves2half2(hx, hy);
    __half2 l2 = __floats2half2_rn(lx, ly);
    lo = *(uint32_t*)&l2;
    return *(uint32_t*)&h2;
}

// ---------------- kernel 1a: A split ----------------
__global__ __launch_bounds__(256)
void convA_kernel(const float* __restrict__ src) {
    int u = blockIdx.x * 8 + (threadIdx.x >> 5);
    int lane = threadIdx.x & 31;
    int mb = u & 63, kc = (u >> 6) & 63, b = u >> 12;
    const float* Ab = src + ((size_t)b * SS + mb * 16) * DD + (size_t)kc * 16;
    int g = lane >> 2, t2 = (lane & 3) * 2;

    uint32_t rh[4], rl[4];
    #pragma unroll
    for (int i = 0; i < 4; i++) {
        int row = g + (i & 1) * 8;
        int col = t2 + (i >> 1) * 8;
        float2 xy = *(const float2*)(Ab + (size_t)row * DD + col);
        rh[i] = pack_hi_lo(xy.x, xy.y, rl[i]);
    }
    size_t o = ((size_t)u * 32 + lane) * 4;
    *(uint4*)(g_Ah + o) = make_uint4(rh[0], rh[1], rh[2], rh[3]);
    *(uint4*)(g_Al + o) = make_uint4(rl[0], rl[1], rl[2], rl[3]);
}

// ---------------- kernel 1b: B split ----------------
__global__ __launch_bounds__(256)
void convB_kernel(const float* __restrict__ src) {
    int u = blockIdx.x * 8 + (threadIdx.x >> 5);
    int lane = threadIdx.x & 31;
    int nb = u & 127, kc = (u >> 7) & 63, b = u >> 13;
    const float* Bb = src + ((size_t)b * SS + nb * 8) * DD + (size_t)kc * 16;
    int g = lane >> 2, t2 = (lane & 3) * 2;

    uint32_t rh[2], rl[2];
    #pragma unroll
    for (int i = 0; i < 2; i++) {
        int col = t2 + i * 8;
        float2 xy = *(const float2*)(Bb + (size_t)g * DD + col);
        rh[i] = pack_hi_lo(xy.x, xy.y, rl[i]);
    }
    size_t o = ((size_t)u * 32 + lane) * 2;
    *(uint2*)(g_Bh + o) = make_uint2(rh[0], rh[1]);
    *(uint2*)(g_Bl + o) = make_uint2(rl[0], rl[1]);
}

// ---------------- kernel 0: masks + lengths ----------------
__global__ void mask_kernel(const int* __restrict__ ids_src,
                            const int* __restrict__ ids_tgt) {
    int b = blockIdx.x;
    int z = blockIdx.y;
    const int* ids = (z == 0 ? ids_src : ids_tgt) + b * SS;
    float* add = (z == 0 ? g_add_src : g_add_tgt) + b * SS;
    int i = threadIdx.x;
    int id = ids[i];
    bool sp = (id == 0) || (id == 101) || (id == 102);
    add[i] = sp ? -10000.0f : 0.0f;

    int v = sp ? 0 : 1;
    #pragma unroll
    for (int o = 16; o; o >>= 1) v += __shfl_xor_sync(0xffffffffu, v, o);
    __shared__ int cnt;
    if (threadIdx.x == 0) cnt = 0;
    __syncthreads();
    if ((threadIdx.x & 31) == 0) atomicAdd(&cnt, v);
    __syncthreads();
    if (threadIdx.x == 0) {
        float inv = rsqrtf((float)cnt);
        if (z == 0) g_invT_src[b] = inv; else g_invT_tgt[b] = inv;
    }
}

// ---------------- kernel 2: 3xFP16 grid-launched GEMM (R12, scores only) ----------------
__global__ __launch_bounds__(256, 2)
void gemm_fp16_kernel() {
    extern __shared__ uint32_t sm[];
    const uint32_t sb = smem_u32(sm);

    const int tid = threadIdx.x;
    const int wid = tid >> 5, lane = tid & 31;
    const int nt = blockIdx.x, mt = blockIdx.y, b = blockIdx.z;

    const int mbase = (wid & 1) * 64;
    const int nbase = (wid >> 1) * 32;

    float acc[4][4][4];
    #pragma unroll
    for (int i = 0; i < 4; i++)
        #pragma unroll
        for (int j = 0; j < 4; j++)
            #pragma unroll
            for (int k = 0; k < 4; k++) acc[i][j][k] = 0.f;

    auto prefetch = [&](int c, int s) {
        uint32_t st = sb + s * STAGE_BYTES;
        int kc0 = 2 * c;
        const uint32_t* srcs[8];
        srcs[0] = g_Ah + (((size_t)b * 64 + kc0    ) * 64 + mt * 8) * 128;
        srcs[1] = g_Ah + (((size_t)b * 64 + kc0 + 1) * 64 + mt * 8) * 128;
        srcs[2] = g_Al + (((size_t)b * 64 + kc0    ) * 64 + mt * 8) * 128;
        srcs[3] = g_Al + (((size_t)b * 64 + kc0 + 1) * 64 + mt * 8) * 128;
        srcs[4] = g_Bh + (((size_t)b * 64 + kc0    ) * 128 + nt * 16) * 64;
        srcs[5] = g_Bh + (((size_t)b * 64 + kc0 + 1) * 128 + nt * 16) * 64;
        srcs[6] = g_Bl + (((size_t)b * 64 + kc0    ) * 128 + nt * 16) * 64;
        srcs[7] = g_Bl + (((size_t)b * 64 + kc0 + 1) * 128 + nt * 16) * 64;
        #pragma unroll
        for (int ch = 0; ch < 8; ch++)
            cp16(st + ch * 4096 + tid * 16, srcs[ch] + tid * 4);
        asm volatile("cp.async.commit_group;" ::: "memory");
    };

    prefetch(0, 0);
    prefetch(1, 1);
    prefetch(2, 2);

    for (int c = 0; c < KC; c++) {
        if (c < KC - 2)       asm volatile("cp.async.wait_group 2;" ::: "memory");
        else if (c == KC - 2) asm volatile("cp.async.wait_group 1;" ::: "memory");
        else                  asm volatile("cp.async.wait_group 0;" ::: "memory");
        __syncthreads();

        uint32_t st = sb + (c % NSTAGE) * STAGE_BYTES;

        #pragma unroll
        for (int ks = 0; ks < 2; ks++) {
            uint32_t ah[4][4], al[4][4], bh[4][2], bl[4][2];
            uint32_t aoff = st + ks * 4096 + ((wid & 1) * 4) * 512 + lane * 16;
            uint32_t boff = st + 16384 + ks * 4096 + ((wid >> 1) * 4) * 256 + lane * 8;
            #pragma unroll
            for (int ms = 0; ms < 4; ms++) LDS128(ah[ms], aoff + ms * 512);
            #pragma unroll
            for (int ms = 0; ms < 4; ms++) LDS128(al[ms], aoff + 8192 + ms * 512);
            #pragma unroll
            for (int ns = 0; ns < 4; ns++) LDS64(bh[ns], boff + ns * 256);
            #pragma unroll
            for (int ns = 0; ns < 4; ns++) LDS64(bl[ns], boff + 8192 + ns * 256);

            #pragma unroll
            for (int ms = 0; ms < 4; ms++)
                #pragma unroll
                for (int ns = 0; ns < 4; ns++)
                    mma_f16(acc[ms][ns], ah[ms], bh[ns]);
            #pragma unroll
            for (int ms = 0; ms < 4; ms++)
                #pragma unroll
                for (int ns = 0; ns < 4; ns++)
                    mma_f16(acc[ms][ns], ah[ms], bl[ns]);
            #pragma unroll
            for (int ms = 0; ms < 4; ms++)
                #pragma unroll
                for (int ns = 0; ns < 4; ns++)
                    mma_f16(acc[ms][ns], al[ms], bh[ns]);
        }
        __syncthreads();
        if (c + NSTAGE < KC) prefetch(c + NSTAGE, c % NSTAGE);
    }

    float* Cb = g_scores + (size_t)b * SS * SS;
    int row0 = mt * TMB + mbase;
    int col0 = nt * TNB + nbase;
    #pragma unroll
    for (int ms = 0; ms < 4; ms++) {
        #pragma unroll
        for (int ns = 0; ns < 4; ns++) {
            int r = row0 + ms * 16 + (lane >> 2);
            int cc = col0 + ns * 8 + 2 * (lane & 3);
            *(float2*)(Cb + (size_t)r * SS + cc) =
                make_float2(acc[ms][ns][0], acc[ms][ns][1]);
            *(float2*)(Cb + (size_t)(r + 8) * SS + cc) =
                make_float2(acc[ms][ns][2], acc[ms][ns][3]);
        }
    }
}

// ---------------- kernel 3a: column-stat partials ----------------
__global__ __launch_bounds__(128)
void colpart_kernel() {
    const int b = blockIdx.z;
    const int rc = blockIdx.y;
    const int col = blockIdx.x * 128 + threadIdx.x;
    const float invT = g_invT_src[b];
    const int rows = SS / RCHUNKS;
    const float* sc = g_scores + (size_t)b * SS * SS + (size_t)rc * rows * SS + col;
    const float* as = g_add_src + (b << 10) + rc * rows;

    float m = -INFINITY, s1 = 0.f, sT = 0.f;
    #pragma unroll 1
    for (int s = 0; s < rows; s += 4) {
        float x0 = sc[(size_t)(s + 0) * SS] + as[s + 0];
        float x1 = sc[(size_t)(s + 1) * SS] + as[s + 1];
        float x2 = sc[(size_t)(s + 2) * SS] + as[s + 2];
        float x3 = sc[(size_t)(s + 3) * SS] + as[s + 3];
        float xs[4] = {x0, x1, x2, x3};
        #pragma unroll
        for (int j = 0; j < 4; j++) {
            float x = xs[j];
            if (x > m) {
                float r1 = __expf(m - x), rT = __expf((m - x) * invT);
                s1 = s1 * r1 + 1.0f;
                sT = sT * rT + 1.0f;
                m = x;
            } else {
                s1 += __expf(x - m);
                sT += __expf((x - m) * invT);
            }
        }
    }
    int idx = b * SS + col;
    g_cm[rc][idx] = m;
    g_c1[rc][idx] = s1;
    g_cT[rc][idx] = sT;
}

// ---------------- kernel 3b: combine column partials + log-threshold ----------------
__global__ void colcombine_kernel() {
    int i = blockIdx.x * blockDim.x + threadIdx.x;
    int b = i >> 10;
    float invT = g_invT_src[b];

    float M = -INFINITY;
    #pragma unroll
    for (int rc = 0; rc < RCHUNKS; rc++) M = fmaxf(M, g_cm[rc][i]);
    float S1 = 0.f, ST = 0.f;
    #pragma unroll
    for (int rc = 0; rc < RCHUNKS; rc++) {
        float d = g_cm[rc][i] - M;
        S1 += g_c1[rc][i] * __expf(d);
        ST += g_cT[rc][i] * __expf(d * invT);
    }
    g_colmax[i] = M;
    g_colsumT[i] = ST;
    g_colth[i] = M + __logf(1e-3f * S1);
}

// ---------------- kernel 4: warp-per-row fused rowstats + output ----------------
__global__ __launch_bounds__(256)
void out_kernel(float* __restrict__ out, size_t half) {
    int wid = threadIdx.x >> 5, lane = threadIdx.x & 31;
    int row = blockIdx.x * 8 + wid;
    int b = row >> 10;
    const float* sr = g_scores + (size_t)row * SS;
    const float* at = g_add_tgt + (b << 10);
    float invTr = g_invT_tgt[b];
    float invTc = g_invT_src[b];
    float adds = g_add_src[row];

    // pass 1: load masked row, find max (warp-local, shfl only)
    float x[32];
    float m = -INFINITY;
    #pragma unroll
    for (int i = 0; i < 8; i++) {
        int t0 = i * 128 + lane * 4;
        float4 v = *(const float4*)(sr + t0);
        float4 a = *(const float4*)(at + t0);
        x[i * 4 + 0] = v.x + a.x; x[i * 4 + 1] = v.y + a.y;
        x[i * 4 + 2] = v.z + a.z; x[i * 4 + 3] = v.w + a.w;
        m = fmaxf(m, fmaxf(fmaxf(x[i * 4], x[i * 4 + 1]),
                           fmaxf(x[i * 4 + 2], x[i * 4 + 3])));
    }
    #pragma unroll
    for (int o = 16; o; o >>= 1) m = fmaxf(m, __shfl_xor_sync(0xffffffffu, m, o));

    // pass 2: exps + sums
    float e1[32], eT[32];
    float s1 = 0.f, sT = 0.f;
    #pragma unroll
    for (int j = 0; j < 32; j++) {
        e1[j] = __expf(x[j] - m);
        eT[j] = __expf((x[j] - m) * invTr);
        s1 += e1[j]; sT += eT[j];
    }
    #pragma unroll
    for (int o = 16; o; o >>= 1) {
        s1 += __shfl_xor_sync(0xffffffffu, s1, o);
        sT += __shfl_xor_sync(0xffffffffu, sT, o);
    }
    float inv_rsT = 1.0f / sT;
    float th_row = 1e-3f * s1;

    // pass 3: outputs
    const float* thP = g_colth   + (b << 10);
    const float* cmP = g_colmax  + (b << 10);
    const float* cTP = g_colsumT + (b << 10);
    size_t rbase = (size_t)row * SS;
    #pragma unroll
    for (int i = 0; i < 8; i++) {
        int t0 = i * 128 + lane * 4;
        float4 th = *(const float4*)(thP + t0);
        float4 cm = *(const float4*)(cmP + t0);
        float4 cT = *(const float4*)(cTP + t0);
        float4 a  = *(const float4*)(at + t0);
        float thv[4] = {th.x, th.y, th.z, th.w};
        float cmv[4] = {cm.x, cm.y, cm.z, cm.w};
        float cTv[4] = {cT.x, cT.y, cT.z, cT.w};
        float av[4]  = {a.x, a.y, a.z, a.w};

        float al[4], pr[4];
        #pragma unroll
        for (int j = 0; j < 4; j++) {
            float xv = x[i * 4 + j];
            float xt = xv - av[j] + adds;          // raw score + add_src
            float psT = eT[i * 4 + j] * inv_rsT;
            float ptT = __expf((xt - cmv[j]) * invTc) / cTv[j];
            al[j] = (e1[i * 4 + j] > th_row && xt > thv[j]) ? 1.0f : 0.0f;
            pr[j] = 2.0f * psT * ptT / (psT + ptT + 1e-9f);
        }
        *(float4*)(out + rbase + t0)        = make_float4(al[0], al[1], al[2], al[3]);
        *(float4*)(out + half + rbase + t0) = make_float4(pr[0], pr[1], pr[2], pr[3]);
    }
}

// ---------------- launch ----------------
extern "C" void kernel_launch(void* const* d_in, const int* in_sizes, int n_in,
                              void* d_out, int out_size) {
    const float* hs  = (const float*)d_in[0];
    const float* ht  = (const float*)d_in[1];
    const int*   isr = (const int*)d_in[2];
    const int*   itg = (const int*)d_in[3];
    float* out = (float*)d_out;

    static bool attr_set = false;
    if (!attr_set) {
        cudaFuncSetAttribute(gemm_fp16_kernel,
                             cudaFuncAttributeMaxDynamicSharedMemorySize, GEMM_SMEM);
        attr_set = true;
    }

    convA_kernel<<<16 * 64 * 64 / 8, 256>>>(hs);                     // launch 1
    convB_kernel<<<16 * 64 * 128 / 8, 256>>>(ht);                    // launch 2
    mask_kernel<<<dim3(BB, 2), SS>>>(isr, itg);                      // launch 3
    gemm_fp16_kernel<<<dim3(SS / TNB, SS / TMB, BB), 256, GEMM_SMEM>>>();  // launch 4 (profiled)
    colpart_kernel<<<dim3(SS / 128, RCHUNKS, BB), 128>>>();          // launch 5
    colcombine_kernel<<<BB * SS / 256, 256>>>();                     // launch 6
    out_kernel<<<BB * SS / 8, 256>>>(out, (size_t)out_size / 2);     // launch 7
}

// round 15
// speedup vs baseline: 1.2004x; 1.2004x over previous
#include <cuda_runtime.h>
#include <cuda_fp16.h>
#include <cstdint>
#include <math.h>

#define BB 16
#define SS 1024
#define DD 1024
#define RCHUNKS 16

#define TMB 128
#define TNB 128
#define KC 32
#define STAGE_BYTES 32768
#define NSTAGE 3
#define GEMM_SMEM (NSTAGE * STAGE_BYTES)   // 98304

// ---------------- scratch ----------------
__device__ float g_scores[BB * SS * SS];
__device__ uint32_t g_Ah[16 * 64 * 64 * 32 * 4];
__device__ uint32_t g_Al[16 * 64 * 64 * 32 * 4];
__device__ uint32_t g_Bh[16 * 64 * 128 * 32 * 2];
__device__ uint32_t g_Bl[16 * 64 * 128 * 32 * 2];
__device__ float g_add_src[BB * SS];
__device__ float g_add_tgt[BB * SS];
__device__ float g_invT_src[BB];
__device__ float g_invT_tgt[BB];
__device__ float g_colmax[BB * SS];
__device__ float g_colrcpT[BB * SS];              // 1 / colsumT
__device__ float g_colth[BB * SS];                // colmax + ln(1e-3 * colsum1)
__device__ float g_cm[RCHUNKS][BB * SS];
__device__ float g_c1[RCHUNKS][BB * SS];
__device__ float g_cT[RCHUNKS][BB * SS];

// ---------------- helpers ----------------
__device__ __forceinline__ uint32_t smem_u32(const void* p) {
    uint32_t a;
    asm("{ .reg .u64 t; cvta.to.shared.u64 t, %1; cvt.u32.u64 %0, t; }"
        : "=r"(a) : "l"(p));
    return a;
}

__device__ __forceinline__ void mma_f16(float* c, const uint32_t* a, const uint32_t* b) {
    asm volatile(
        "mma.sync.aligned.m16n8k16.row.col.f32.f16.f16.f32 "
        "{%0,%1,%2,%3}, {%4,%5,%6,%7}, {%8,%9}, {%0,%1,%2,%3};"
        : "+f"(c[0]), "+f"(c[1]), "+f"(c[2]), "+f"(c[3])
        : "r"(a[0]), "r"(a[1]), "r"(a[2]), "r"(a[3]), "r"(b[0]), "r"(b[1]));
}

__device__ __forceinline__ void cp16(uint32_t dst, const void* src) {
    asm volatile("cp.async.cg.shared.global [%0], [%1], 16;"
                 :: "r"(dst), "l"(src) : "memory");
}

#define LDS128(r, addr) \
    asm volatile("ld.shared.v4.b32 {%0,%1,%2,%3}, [%4];" \
        : "=r"((r)[0]), "=r"((r)[1]), "=r"((r)[2]), "=r"((r)[3]) : "r"(addr))
#define LDS64(r, addr) \
    asm volatile("ld.shared.v2.b32 {%0,%1}, [%2];" \
        : "=r"((r)[0]), "=r"((r)[1]) : "r"(addr))

__device__ __forceinline__ uint32_t pack_hi_lo(float x, float y, uint32_t& lo) {
    __half hx = __float2half_rn(x), hy = __float2half_rn(y);
    float lx = x - __half2float(hx), ly = y - __half2float(hy);
    __half2 h2 = __halves2half2(hx, hy);
    __half2 l2 = __floats2half2_rn(lx, ly);
    lo = *(uint32_t*)&l2;
    return *(uint32_t*)&h2;
}

// ---------------- kernel 1a: A split ----------------
__global__ __launch_bounds__(256)
void convA_kernel(const float* __restrict__ src) {
    int u = blockIdx.x * 8 + (threadIdx.x >> 5);
    int lane = threadIdx.x & 31;
    int mb = u & 63, kc = (u >> 6) & 63, b = u >> 12;
    const float* Ab = src + ((size_t)b * SS + mb * 16) * DD + (size_t)kc * 16;
    int g = lane >> 2, t2 = (lane & 3) * 2;

    uint32_t rh[4], rl[4];
    #pragma unroll
    for (int i = 0; i < 4; i++) {
        int row = g + (i & 1) * 8;
        int col = t2 + (i >> 1) * 8;
        float2 xy = *(const float2*)(Ab + (size_t)row * DD + col);
        rh[i] = pack_hi_lo(xy.x, xy.y, rl[i]);
    }
    size_t o = ((size_t)u * 32 + lane) * 4;
    *(uint4*)(g_Ah + o) = make_uint4(rh[0], rh[1], rh[2], rh[3]);
    *(uint4*)(g_Al + o) = make_uint4(rl[0], rl[1], rl[2], rl[3]);
}

// ---------------- kernel 1b: B split ----------------
__global__ __launch_bounds__(256)
void convB_kernel(const float* __restrict__ src) {
    int u = blockIdx.x * 8 + (threadIdx.x >> 5);
    int lane = threadIdx.x & 31;
    int nb = u & 127, kc = (u >> 7) & 63, b = u >> 13;
    const float* Bb = src + ((size_t)b * SS + nb * 8) * DD + (size_t)kc * 16;
    int g = lane >> 2, t2 = (lane & 3) * 2;

    uint32_t rh[2], rl[2];
    #pragma unroll
    for (int i = 0; i < 2; i++) {
        int col = t2 + i * 8;
        float2 xy = *(const float2*)(Bb + (size_t)g * DD + col);
        rh[i] = pack_hi_lo(xy.x, xy.y, rl[i]);
    }
    size_t o = ((size_t)u * 32 + lane) * 2;
    *(uint2*)(g_Bh + o) = make_uint2(rh[0], rh[1]);
    *(uint2*)(g_Bl + o) = make_uint2(rl[0], rl[1]);
}

// ---------------- kernel 0: masks + lengths ----------------
__global__ void mask_kernel(const int* __restrict__ ids_src,
                            const int* __restrict__ ids_tgt) {
    int b = blockIdx.x;
    int z = blockIdx.y;
    const int* ids = (z == 0 ? ids_src : ids_tgt) + b * SS;
    float* add = (z == 0 ? g_add_src : g_add_tgt) + b * SS;
    int i = threadIdx.x;
    int id = ids[i];
    bool sp = (id == 0) || (id == 101) || (id == 102);
    add[i] = sp ? -10000.0f : 0.0f;

    int v = sp ? 0 : 1;
    #pragma unroll
    for (int o = 16; o; o >>= 1) v += __shfl_xor_sync(0xffffffffu, v, o);
    __shared__ int cnt;
    if (threadIdx.x == 0) cnt = 0;
    __syncthreads();
    if ((threadIdx.x & 31) == 0) atomicAdd(&cnt, v);
    __syncthreads();
    if (threadIdx.x == 0) {
        float inv = rsqrtf((float)cnt);
        if (z == 0) g_invT_src[b] = inv; else g_invT_tgt[b] = inv;
    }
}

// ---------------- kernel 2: 3xFP16 grid-launched GEMM (R12, scores only) ----------------
__global__ __launch_bounds__(256, 2)
void gemm_fp16_kernel() {
    extern __shared__ uint32_t sm[];
    const uint32_t sb = smem_u32(sm);

    const int tid = threadIdx.x;
    const int wid = tid >> 5, lane = tid & 31;
    const int nt = blockIdx.x, mt = blockIdx.y, b = blockIdx.z;

    const int mbase = (wid & 1) * 64;
    const int nbase = (wid >> 1) * 32;

    float acc[4][4][4];
    #pragma unroll
    for (int i = 0; i < 4; i++)
        #pragma unroll
        for (int j = 0; j < 4; j++)
            #pragma unroll
            for (int k = 0; k < 4; k++) acc[i][j][k] = 0.f;

    auto prefetch = [&](int c, int s) {
        uint32_t st = sb + s * STAGE_BYTES;
        int kc0 = 2 * c;
        const uint32_t* srcs[8];
        srcs[0] = g_Ah + (((size_t)b * 64 + kc0    ) * 64 + mt * 8) * 128;
        srcs[1] = g_Ah + (((size_t)b * 64 + kc0 + 1) * 64 + mt * 8) * 128;
        srcs[2] = g_Al + (((size_t)b * 64 + kc0    ) * 64 + mt * 8) * 128;
        srcs[3] = g_Al + (((size_t)b * 64 + kc0 + 1) * 64 + mt * 8) * 128;
        srcs[4] = g_Bh + (((size_t)b * 64 + kc0    ) * 128 + nt * 16) * 64;
        srcs[5] = g_Bh + (((size_t)b * 64 + kc0 + 1) * 128 + nt * 16) * 64;
        srcs[6] = g_Bl + (((size_t)b * 64 + kc0    ) * 128 + nt * 16) * 64;
        srcs[7] = g_Bl + (((size_t)b * 64 + kc0 + 1) * 128 + nt * 16) * 64;
        #pragma unroll
        for (int ch = 0; ch < 8; ch++)
            cp16(st + ch * 4096 + tid * 16, srcs[ch] + tid * 4);
        asm volatile("cp.async.commit_group;" ::: "memory");
    };

    prefetch(0, 0);
    prefetch(1, 1);
    prefetch(2, 2);

    for (int c = 0; c < KC; c++) {
        if (c < KC - 2)       asm volatile("cp.async.wait_group 2;" ::: "memory");
        else if (c == KC - 2) asm volatile("cp.async.wait_group 1;" ::: "memory");
        else                  asm volatile("cp.async.wait_group 0;" ::: "memory");
        __syncthreads();

        uint32_t st = sb + (c % NSTAGE) * STAGE_BYTES;

        #pragma unroll
        for (int ks = 0; ks < 2; ks++) {
            uint32_t ah[4][4], al[4][4], bh[4][2], bl[4][2];
            uint32_t aoff = st + ks * 4096 + ((wid & 1) * 4) * 512 + lane * 16;
            uint32_t boff = st + 16384 + ks * 4096 + ((wid >> 1) * 4) * 256 + lane * 8;
            #pragma unroll
            for (int ms = 0; ms < 4; ms++) LDS128(ah[ms], aoff + ms * 512);
            #pragma unroll
            for (int ms = 0; ms < 4; ms++) LDS128(al[ms], aoff + 8192 + ms * 512);
            #pragma unroll
            for (int ns = 0; ns < 4; ns++) LDS64(bh[ns], boff + ns * 256);
            #pragma unroll
            for (int ns = 0; ns < 4; ns++) LDS64(bl[ns], boff + 8192 + ns * 256);

            #pragma unroll
            for (int ms = 0; ms < 4; ms++)
                #pragma unroll
                for (int ns = 0; ns < 4; ns++)
                    mma_f16(acc[ms][ns], ah[ms], bh[ns]);
            #pragma unroll
            for (int ms = 0; ms < 4; ms++)
                #pragma unroll
                for (int ns = 0; ns < 4; ns++)
                    mma_f16(acc[ms][ns], ah[ms], bl[ns]);
            #pragma unroll
            for (int ms = 0; ms < 4; ms++)
                #pragma unroll
                for (int ns = 0; ns < 4; ns++)
                    mma_f16(acc[ms][ns], al[ms], bh[ns]);
        }
        __syncthreads();
        if (c + NSTAGE < KC) prefetch(c + NSTAGE, c % NSTAGE);
    }

    float* Cb = g_scores + (size_t)b * SS * SS;
    int row0 = mt * TMB + mbase;
    int col0 = nt * TNB + nbase;
    #pragma unroll
    for (int ms = 0; ms < 4; ms++) {
        #pragma unroll
        for (int ns = 0; ns < 4; ns++) {
            int r = row0 + ms * 16 + (lane >> 2);
            int cc = col0 + ns * 8 + 2 * (lane & 3);
            *(float2*)(Cb + (size_t)r * SS + cc) =
                make_float2(acc[ms][ns][0], acc[ms][ns][1]);
            *(float2*)(Cb + (size_t)(r + 8) * SS + cc) =
                make_float2(acc[ms][ns][2], acc[ms][ns][3]);
        }
    }
}

// ---------------- kernel 3a: column-stat partials ----------------
__global__ __launch_bounds__(128)
void colpart_kernel() {
    const int b = blockIdx.z;
    const int rc = blockIdx.y;
    const int col = blockIdx.x * 128 + threadIdx.x;
    const float invT = g_invT_src[b];
    const int rows = SS / RCHUNKS;
    const float* sc = g_scores + (size_t)b * SS * SS + (size_t)rc * rows * SS + col;
    const float* as = g_add_src + (b << 10) + rc * rows;

    float m = -INFINITY, s1 = 0.f, sT = 0.f;
    #pragma unroll 1
    for (int s = 0; s < rows; s += 4) {
        float x0 = sc[(size_t)(s + 0) * SS] + as[s + 0];
        float x1 = sc[(size_t)(s + 1) * SS] + as[s + 1];
        float x2 = sc[(size_t)(s + 2) * SS] + as[s + 2];
        float x3 = sc[(size_t)(s + 3) * SS] + as[s + 3];
        float xs[4] = {x0, x1, x2, x3};
        #pragma unroll
        for (int j = 0; j < 4; j++) {
            float x = xs[j];
            if (x > m) {
                float r1 = __expf(m - x), rT = __expf((m - x) * invT);
                s1 = s1 * r1 + 1.0f;
                sT = sT * rT + 1.0f;
                m = x;
            } else {
                s1 += __expf(x - m);
                sT += __expf((x - m) * invT);
            }
        }
    }
    int idx = b * SS + col;
    g_cm[rc][idx] = m;
    g_c1[rc][idx] = s1;
    g_cT[rc][idx] = sT;
}

// ---------------- kernel 3b: combine column partials + log-threshold + rcp ----------------
__global__ void colcombine_kernel() {
    int i = blockIdx.x * blockDim.x + threadIdx.x;
    int b = i >> 10;
    float invT = g_invT_src[b];

    float M = -INFINITY;
    #pragma unroll
    for (int rc = 0; rc < RCHUNKS; rc++) M = fmaxf(M, g_cm[rc][i]);
    float S1 = 0.f, ST = 0.f;
    #pragma unroll
    for (int rc = 0; rc < RCHUNKS; rc++) {
        float d = g_cm[rc][i] - M;
        S1 += g_c1[rc][i] * __expf(d);
        ST += g_cT[rc][i] * __expf(d * invT);
    }
    g_colmax[i] = M;
    g_colrcpT[i] = 1.0f / ST;
    g_colth[i] = M + __logf(1e-3f * S1);
}

// ---------------- kernel 4: fused rowstats + output (div-free inner loop) ----------------
__global__ __launch_bounds__(256)
void out_kernel(float* __restrict__ out, size_t half) {
    int row = blockIdx.x;
    int b = row >> 10;
    const float* sr = g_scores + (size_t)row * SS;
    const float* at = g_add_tgt + (b << 10);
    float invTr = g_invT_tgt[b];
    float invTc = g_invT_src[b];
    float adds = g_add_src[row];

    int t0 = threadIdx.x * 4;
    float4 v = *(const float4*)(sr + t0);
    float4 a = *(const float4*)(at + t0);
    float xv[4] = {v.x + a.x, v.y + a.y, v.z + a.z, v.w + a.w};

    float m = fmaxf(fmaxf(xv[0], xv[1]), fmaxf(xv[2], xv[3]));
    #pragma unroll
    for (int o = 16; o; o >>= 1) m = fmaxf(m, __shfl_xor_sync(0xffffffffu, m, o));
    __shared__ float redm[8];
    int wid = threadIdx.x >> 5, lane = threadIdx.x & 31;
    if (lane == 0) redm[wid] = m;
    __syncthreads();
    m = redm[0];
    #pragma unroll
    for (int w = 1; w < 8; w++) m = fmaxf(m, redm[w]);

    float e1[4], eT[4];
    float s1 = 0.f, sT = 0.f;
    #pragma unroll
    for (int j = 0; j < 4; j++) {
        e1[j] = __expf(xv[j] - m);
        eT[j] = __expf((xv[j] - m) * invTr);
        s1 += e1[j]; sT += eT[j];
    }
    #pragma unroll
    for (int o = 16; o; o >>= 1) {
        s1 += __shfl_xor_sync(0xffffffffu, s1, o);
        sT += __shfl_xor_sync(0xffffffffu, sT, o);
    }
    __shared__ float r1[8], rT[8];
    if (lane == 0) { r1[wid] = s1; rT[wid] = sT; }
    __syncthreads();
    float S1 = 0.f, ST = 0.f;
    #pragma unroll
    for (int w = 0; w < 8; w++) { S1 += r1[w]; ST += rT[w]; }
    float inv_rsT = __fdividef(1.0f, ST);
    float th_row = 1e-3f * S1;

    float4 th = *(const float4*)(g_colth   + (b << 10) + t0);
    float4 cm = *(const float4*)(g_colmax  + (b << 10) + t0);
    float4 cR = *(const float4*)(g_colrcpT + (b << 10) + t0);
    float thv[4] = {th.x, th.y, th.z, th.w};
    float cmv[4] = {cm.x, cm.y, cm.z, cm.w};
    float cRv[4] = {cR.x, cR.y, cR.z, cR.w};
    float rawv[4] = {v.x, v.y, v.z, v.w};

    float al[4], pr[4];
    #pragma unroll
    for (int j = 0; j < 4; j++) {
        float xt = rawv[j] + adds;
        float psT = eT[j] * inv_rsT;
        float ptT = __expf((xt - cmv[j]) * invTc) * cRv[j];
        al[j] = (e1[j] > th_row && xt > thv[j]) ? 1.0f : 0.0f;
        pr[j] = __fdividef(2.0f * psT * ptT, psT + ptT + 1e-9f);
    }
    size_t base = (size_t)row * SS + t0;
    *(float4*)(out + base)        = make_float4(al[0], al[1], al[2], al[3]);
    *(float4*)(out + half + base) = make_float4(pr[0], pr[1], pr[2], pr[3]);
}

// ---------------- launch ----------------
extern "C" void kernel_launch(void* const* d_in, const int* in_sizes, int n_in,
                              void* d_out, int out_size) {
    const float* hs  = (const float*)d_in[0];
    const float* ht  = (const float*)d_in[1];
    const int*   isr = (const int*)d_in[2];
    const int*   itg = (const int*)d_in[3];
    float* out = (float*)d_out;

    static bool attr_set = false;
    if (!attr_set) {
        cudaFuncSetAttribute(gemm_fp16_kernel,
                             cudaFuncAttributeMaxDynamicSharedMemorySize, GEMM_SMEM);
        attr_set = true;
    }

    convA_kernel<<<16 * 64 * 64 / 8, 256>>>(hs);                     // launch 1
    convB_kernel<<<16 * 64 * 128 / 8, 256>>>(ht);                    // launch 2
    mask_kernel<<<dim3(BB, 2), SS>>>(isr, itg);                      // launch 3
    gemm_fp16_kernel<<<dim3(SS / TNB, SS / TMB, BB), 256, GEMM_SMEM>>>();  // launch 4 (profiled)
    colpart_kernel<<<dim3(SS / 128, RCHUNKS, BB), 128>>>();          // launch 5
    colcombine_kernel<<<BB * SS / 256, 256>>>();                     // launch 6
    out_kernel<<<BB * SS, 256>>>(out, (size_t)out_size / 2);         // launch 7
}